// round 4
// baseline (speedup 1.0000x reference)
#include <cuda_runtime.h>
#include <cuda_fp16.h>
#include <math.h>

#define N_NODES 50000
#define N_EDGES 800000
#define DIN 128

// ---------------- scratch (no cudaMalloc allowed) ----------------
__device__ __half g_h0[N_NODES * DIN];
__device__ __half g_h1[N_NODES * DIN];
__device__ __half g_xp[N_NODES * DIN];
__device__ __half g_pooled[N_NODES * DIN];
__device__ int    g_rowptr[N_NODES + 1];
__device__ int    g_cursor[N_NODES];
__device__ int    g_csr[N_EDGES];

struct alignas(8) H4 { __half2 a, b; };

// ---------------- CSR build ----------------
__global__ void count_deg_kernel(const int4* __restrict__ dst4) {
    int i = blockIdx.x * blockDim.x + threadIdx.x;
    if (i < N_EDGES / 4) {
        int4 d = dst4[i];
        atomicAdd(&g_cursor[d.x], 1);
        atomicAdd(&g_cursor[d.y], 1);
        atomicAdd(&g_cursor[d.z], 1);
        atomicAdd(&g_cursor[d.w], 1);
    }
}

// thread-coarsened block scan: 1024 threads x 49 elems, one shuffle scan
__global__ void scan_kernel() {
    const int T = 1024;
    const int CH = (N_NODES + T - 1) / T;  // 49
    int tid = threadIdx.x;
    int start = tid * CH;

    int vals[CH];
    int s = 0;
    #pragma unroll
    for (int j = 0; j < CH; j++) {
        int i = start + j;
        int v = (i < N_NODES) ? g_cursor[i] : 0;
        vals[j] = v; s += v;
    }
    int lane = tid & 31, w = tid >> 5;
    int inc = s;
    #pragma unroll
    for (int off = 1; off < 32; off <<= 1) {
        int t = __shfl_up_sync(0xffffffffu, inc, off);
        if (lane >= off) inc += t;
    }
    __shared__ int wsum[32];
    if (lane == 31) wsum[w] = inc;
    __syncthreads();
    if (w == 0) {
        int x = wsum[lane];
        #pragma unroll
        for (int off = 1; off < 32; off <<= 1) {
            int t = __shfl_up_sync(0xffffffffu, x, off);
            if (lane >= off) x += t;
        }
        wsum[lane] = x;
    }
    __syncthreads();
    int excl = inc - s + (w > 0 ? wsum[w - 1] : 0);
    #pragma unroll
    for (int j = 0; j < CH; j++) {
        int i = start + j;
        if (i < N_NODES) { g_rowptr[i] = excl; g_cursor[i] = excl; excl += vals[j]; }
    }
    if (tid == T - 1) g_rowptr[N_NODES] = excl;
}

__global__ void scatter_kernel(const int4* __restrict__ src4, const int4* __restrict__ dst4) {
    int i = blockIdx.x * blockDim.x + threadIdx.x;
    if (i < N_EDGES / 4) {
        int4 s = src4[i];
        int4 d = dst4[i];
        int p0 = atomicAdd(&g_cursor[d.x], 1);
        int p1 = atomicAdd(&g_cursor[d.y], 1);
        int p2 = atomicAdd(&g_cursor[d.z], 1);
        int p3 = atomicAdd(&g_cursor[d.w], 1);
        g_csr[p0] = s.x; g_csr[p1] = s.y; g_csr[p2] = s.z; g_csr[p3] = s.w;
    }
}

// ---------------- pooling: per-node warp max over CSR neighbors (fp16) --------
// relu output >= 0, so 0-init max == segment_max (and deg==0 -> 0, matching ref)
__global__ void pool_kernel() {
    int node = (blockIdx.x * blockDim.x + threadIdx.x) >> 5;
    int lane = threadIdx.x & 31;
    if (node >= N_NODES) return;
    int s = g_rowptr[node];
    int e = g_rowptr[node + 1];
    __half2 m0 = __float2half2_rn(0.f), m1 = m0;
    int j = s;
    for (; j + 4 <= e; j += 4) {
        int i0 = g_csr[j], i1 = g_csr[j + 1], i2 = g_csr[j + 2], i3 = g_csr[j + 3];
        H4 v0 = *reinterpret_cast<const H4*>(g_xp + (size_t)i0 * DIN + lane * 4);
        H4 v1 = *reinterpret_cast<const H4*>(g_xp + (size_t)i1 * DIN + lane * 4);
        H4 v2 = *reinterpret_cast<const H4*>(g_xp + (size_t)i2 * DIN + lane * 4);
        H4 v3 = *reinterpret_cast<const H4*>(g_xp + (size_t)i3 * DIN + lane * 4);
        m0 = __hmax2(m0, v0.a); m1 = __hmax2(m1, v0.b);
        m0 = __hmax2(m0, v1.a); m1 = __hmax2(m1, v1.b);
        m0 = __hmax2(m0, v2.a); m1 = __hmax2(m1, v2.b);
        m0 = __hmax2(m0, v3.a); m1 = __hmax2(m1, v3.b);
    }
    for (; j < e; j++) {
        int i0 = g_csr[j];
        H4 v = *reinterpret_cast<const H4*>(g_xp + (size_t)i0 * DIN + lane * 4);
        m0 = __hmax2(m0, v.a); m1 = __hmax2(m1, v.b);
    }
    H4 o; o.a = m0; o.b = m1;
    *reinterpret_cast<H4*>(g_pooled + (size_t)node * DIN + lane * 4) = o;
}

// ---------------- fp16 tensor-core GEMM (m16n8k16, ldmatrix-fed) -------------
__device__ __forceinline__ void ldsm_x4(unsigned& r0, unsigned& r1, unsigned& r2, unsigned& r3,
                                        unsigned addr) {
    asm volatile("ldmatrix.sync.aligned.m8n8.x4.shared.b16 {%0,%1,%2,%3}, [%4];"
                 : "=r"(r0), "=r"(r1), "=r"(r2), "=r"(r3) : "r"(addr));
}
__device__ __forceinline__ void ldsm_x4_t(unsigned& r0, unsigned& r1, unsigned& r2, unsigned& r3,
                                          unsigned addr) {
    asm volatile("ldmatrix.sync.aligned.m8n8.x4.trans.shared.b16 {%0,%1,%2,%3}, [%4];"
                 : "=r"(r0), "=r"(r1), "=r"(r2), "=r"(r3) : "r"(addr));
}
__device__ __forceinline__ void mma_f16(float& d0, float& d1, float& d2, float& d3,
                                        unsigned a0, unsigned a1, unsigned a2, unsigned a3,
                                        unsigned b0, unsigned b1) {
    asm volatile(
        "mma.sync.aligned.m16n8k16.row.col.f32.f16.f16.f32 "
        "{%0,%1,%2,%3}, {%4,%5,%6,%7}, {%8,%9}, {%0,%1,%2,%3};"
        : "+f"(d0), "+f"(d1), "+f"(d2), "+f"(d3)
        : "r"(a0), "r"(a1), "r"(a2), "r"(a3), "r"(b0), "r"(b1));
}

// BM=128 x BN=DOUT, BK=32, 256 threads (8 warps), double-buffered fp16 smem.
// DUAL: C = A1@B1 + A2@B2 (K=256), A2 fp16.  A1 fp32 or fp16 (A1HALF).
// NORM: +bias, row L2-norm, relu.  else: +bias, relu.  OUTHALF: fp16 output.
template <int DOUT, bool DUAL, bool NORM, bool A1HALF, bool OUTHALF>
__global__ void __launch_bounds__(256, 2)
gemm_tc_kernel(const void* __restrict__ A1v, const __half* __restrict__ A2,
               const float* __restrict__ B1, const float* __restrict__ B2,
               const float* __restrict__ bias, void* __restrict__ outv)
{
    constexpr int BM = 128, BK = 32, BN = DOUT;
    constexpr int WC = BN / 64;            // 2 (BN=128) or 1 (BN=64)
    constexpr int WR = 8 / WC;
    constexpr int MT = (BM / WR) / 16;     // 2 or 1
    constexpr int NT = 8;
    constexpr int KT = DUAL ? 8 : 4;
    constexpr int AST = 40;                // halves; 80B row -> conflict-free LDSM
    constexpr int BST = BN + 8;            // 136 (272B) / 72 (144B)
    constexpr int ASZ = BM * AST;
    constexpr int BSZ = BK * BST;
    constexpr int BF4 = (BK * BN) / (4 * 256);   // 4 / 2

    __shared__ __half AsS[2][ASZ];
    __shared__ __half BsS[2][BSZ];
    __shared__ float ssbuf[2][BM];

    const float* A1f = (const float*)A1v;
    const __half* A1h = (const __half*)A1v;

    int tid = threadIdx.x;
    int lane = tid & 31, wid = tid >> 5;
    int lr = lane >> 2, lc = lane & 3;
    int wr = wid / WC, wcid = wid % WC;
    int mbase = wr * (BM / WR);
    int nbase = wcid * 64;
    int blockRow = blockIdx.x * BM;

    int l15 = lane & 15;
    int lhi8 = (lane >> 4) << 3;

    float acc[MT][NT][4];
    #pragma unroll
    for (int mt = 0; mt < MT; mt++)
        #pragma unroll
        for (int nt = 0; nt < NT; nt++)
            #pragma unroll
            for (int r = 0; r < 4; r++) acc[mt][nt][r] = 0.f;

    float4 fav[4];
    uint4  hav[2];
    float4 bvr[BF4];

    auto ldg_tile = [&](int kt) {
        int kb = (kt & 3) * BK;
        const float* B = (!DUAL || kt < 4) ? B1 : B2;
        #pragma unroll
        for (int i = 0; i < BF4; i++) {
            int f = tid + i * 256;
            int brow = f / (BN / 4), bc4 = f % (BN / 4);
            bvr[i] = *reinterpret_cast<const float4*>(B + (size_t)(kb + brow) * BN + bc4 * 4);
        }
        bool a2 = DUAL && kt >= 4;
        if (!a2 && !A1HALF) {
            #pragma unroll
            for (int i = 0; i < 4; i++) {
                int f = tid + i * 256;
                int row = f >> 3, c4 = f & 7;
                int gr = blockRow + row; if (gr >= N_NODES) gr = N_NODES - 1;
                fav[i] = *reinterpret_cast<const float4*>(A1f + (size_t)gr * DIN + kb + c4 * 4);
            }
        } else {
            const __half* Ah = a2 ? A2 : A1h;
            #pragma unroll
            for (int i = 0; i < 2; i++) {
                int f = tid + i * 256;
                int row = f >> 2, q = f & 3;
                int gr = blockRow + row; if (gr >= N_NODES) gr = N_NODES - 1;
                hav[i] = *reinterpret_cast<const uint4*>(Ah + (size_t)gr * DIN + kb + q * 8);
            }
        }
    };

    auto sts_tile = [&](int kt) {
        __half* As = AsS[kt & 1];
        __half* Bs = BsS[kt & 1];
        #pragma unroll
        for (int i = 0; i < BF4; i++) {
            int f = tid + i * 256;
            int brow = f / (BN / 4), bc4 = f % (BN / 4);
            __half2 lo = __floats2half2_rn(bvr[i].x, bvr[i].y);
            __half2 hi = __floats2half2_rn(bvr[i].z, bvr[i].w);
            *reinterpret_cast<__half2*>(Bs + brow * BST + bc4 * 4)     = lo;
            *reinterpret_cast<__half2*>(Bs + brow * BST + bc4 * 4 + 2) = hi;
        }
        bool a2 = DUAL && kt >= 4;
        if (!a2 && !A1HALF) {
            #pragma unroll
            for (int i = 0; i < 4; i++) {
                int f = tid + i * 256;
                int row = f >> 3, c4 = f & 7;
                __half2 lo = __floats2half2_rn(fav[i].x, fav[i].y);
                __half2 hi = __floats2half2_rn(fav[i].z, fav[i].w);
                *reinterpret_cast<__half2*>(As + row * AST + c4 * 4)     = lo;
                *reinterpret_cast<__half2*>(As + row * AST + c4 * 4 + 2) = hi;
            }
        } else {
            #pragma unroll
            for (int i = 0; i < 2; i++) {
                int f = tid + i * 256;
                int row = f >> 2, q = f & 3;
                *reinterpret_cast<uint4*>(As + row * AST + q * 8) = hav[i];
            }
        }
    };

    ldg_tile(0);
    sts_tile(0);
    __syncthreads();

    for (int kt = 0; kt < KT; kt++) {
        if (kt + 1 < KT) ldg_tile(kt + 1);

        const __half* As = AsS[kt & 1];
        const __half* Bs = BsS[kt & 1];
        unsigned abase = (unsigned)__cvta_generic_to_shared(As);
        unsigned bbase = (unsigned)__cvta_generic_to_shared(Bs);

        #pragma unroll
        for (int ks = 0; ks < 2; ks++) {
            int kk = ks * 16;
            unsigned af[MT][4];
            #pragma unroll
            for (int mt = 0; mt < MT; mt++) {
                unsigned addr = abase + 2 * ((mbase + mt * 16 + l15) * AST + kk + lhi8);
                ldsm_x4(af[mt][0], af[mt][1], af[mt][2], af[mt][3], addr);
            }
            unsigned bf[NT][2];
            #pragma unroll
            for (int np = 0; np < NT / 2; np++) {
                unsigned addr = bbase + 2 * ((kk + l15) * BST + nbase + np * 16 + lhi8);
                unsigned r0, r1, r2, r3;
                ldsm_x4_t(r0, r1, r2, r3, addr);
                bf[2 * np][0] = r0; bf[2 * np][1] = r1;
                bf[2 * np + 1][0] = r2; bf[2 * np + 1][1] = r3;
            }
            #pragma unroll
            for (int mt = 0; mt < MT; mt++)
                #pragma unroll
                for (int nt = 0; nt < NT; nt++)
                    mma_f16(acc[mt][nt][0], acc[mt][nt][1], acc[mt][nt][2], acc[mt][nt][3],
                            af[mt][0], af[mt][1], af[mt][2], af[mt][3],
                            bf[nt][0], bf[nt][1]);
        }

        if (kt + 1 < KT) sts_tile(kt + 1);
        __syncthreads();
    }

    // ---- epilogue ----
    #pragma unroll
    for (int nt = 0; nt < NT; nt++) {
        int col = nbase + nt * 8 + 2 * lc;
        float2 bv = *reinterpret_cast<const float2*>(bias + col);
        #pragma unroll
        for (int mt = 0; mt < MT; mt++) {
            acc[mt][nt][0] += bv.x; acc[mt][nt][1] += bv.y;
            acc[mt][nt][2] += bv.x; acc[mt][nt][3] += bv.y;
        }
    }

    float inv0[MT], inv1[MT];
    if (NORM) {
        #pragma unroll
        for (int mt = 0; mt < MT; mt++) {
            float ssA = 0.f, ssB = 0.f;
            #pragma unroll
            for (int nt = 0; nt < NT; nt++) {
                ssA += acc[mt][nt][0] * acc[mt][nt][0] + acc[mt][nt][1] * acc[mt][nt][1];
                ssB += acc[mt][nt][2] * acc[mt][nt][2] + acc[mt][nt][3] * acc[mt][nt][3];
            }
            ssA += __shfl_xor_sync(0xffffffffu, ssA, 1);
            ssA += __shfl_xor_sync(0xffffffffu, ssA, 2);
            ssB += __shfl_xor_sync(0xffffffffu, ssB, 1);
            ssB += __shfl_xor_sync(0xffffffffu, ssB, 2);
            if (WC == 2) {
                int ra = mbase + mt * 16 + lr;
                if (lc == 0) { ssbuf[wcid][ra] = ssA; ssbuf[wcid][ra + 8] = ssB; }
            } else {
                inv0[mt] = 1.f / fmaxf(sqrtf(ssA), 1e-12f);
                inv1[mt] = 1.f / fmaxf(sqrtf(ssB), 1e-12f);
            }
        }
        if (WC == 2) {
            __syncthreads();
            #pragma unroll
            for (int mt = 0; mt < MT; mt++) {
                int ra = mbase + mt * 16 + lr;
                float tA = ssbuf[0][ra] + ssbuf[1][ra];
                float tB = ssbuf[0][ra + 8] + ssbuf[1][ra + 8];
                inv0[mt] = 1.f / fmaxf(sqrtf(tA), 1e-12f);
                inv1[mt] = 1.f / fmaxf(sqrtf(tB), 1e-12f);
            }
        }
    }

    #pragma unroll
    for (int mt = 0; mt < MT; mt++) {
        int ra = blockRow + mbase + mt * 16 + lr;
        int rb = ra + 8;
        #pragma unroll
        for (int nt = 0; nt < NT; nt++) {
            int col = nbase + nt * 8 + 2 * lc;
            float v0 = acc[mt][nt][0], v1 = acc[mt][nt][1];
            float v2 = acc[mt][nt][2], v3 = acc[mt][nt][3];
            if (NORM) {
                v0 *= inv0[mt]; v1 *= inv0[mt];
                v2 *= inv1[mt]; v3 *= inv1[mt];
            }
            v0 = fmaxf(v0, 0.f); v1 = fmaxf(v1, 0.f);
            v2 = fmaxf(v2, 0.f); v3 = fmaxf(v3, 0.f);
            if (OUTHALF) {
                __half* out = (__half*)outv;
                if (ra < N_NODES)
                    *reinterpret_cast<__half2*>(out + (size_t)ra * DOUT + col) = __floats2half2_rn(v0, v1);
                if (rb < N_NODES)
                    *reinterpret_cast<__half2*>(out + (size_t)rb * DOUT + col) = __floats2half2_rn(v2, v3);
            } else {
                float* out = (float*)outv;
                if (ra < N_NODES)
                    *reinterpret_cast<float2*>(out + (size_t)ra * DOUT + col) = make_float2(v0, v1);
                if (rb < N_NODES)
                    *reinterpret_cast<float2*>(out + (size_t)rb * DOUT + col) = make_float2(v2, v3);
            }
        }
    }
}

// ---------------- launch ----------------
extern "C" void kernel_launch(void* const* d_in, const int* in_sizes, int n_in,
                              void* d_out, int out_size)
{
    const float* x        = (const float*)d_in[0];
    const int*   edge_src = (const int*)d_in[1];
    const int*   edge_dst = (const int*)d_in[2];

    const float* Wp[3]; const float* bp[3];
    const float* Ws[3]; const float* Wn[3]; const float* bb[3];
    for (int l = 0; l < 3; l++) {
        Wp[l] = (const float*)d_in[3 + 5 * l + 0];
        bp[l] = (const float*)d_in[3 + 5 * l + 1];
        Ws[l] = (const float*)d_in[3 + 5 * l + 2];
        Wn[l] = (const float*)d_in[3 + 5 * l + 3];
        bb[l] = (const float*)d_in[3 + 5 * l + 4];
    }

    float* out = (float*)d_out;

    __half* h0d; cudaGetSymbolAddress((void**)&h0d, g_h0);
    __half* h1d; cudaGetSymbolAddress((void**)&h1d, g_h1);
    __half* xpd; cudaGetSymbolAddress((void**)&xpd, g_xp);
    __half* pld; cudaGetSymbolAddress((void**)&pld, g_pooled);
    int* curd;  cudaGetSymbolAddress((void**)&curd, g_cursor);

    const int TPB = 256;
    const int GEMM_BLOCKS = (N_NODES + 127) / 128;              // 391
    const int EDGE4_BLOCKS = (N_EDGES / 4 + TPB - 1) / TPB;
    const int POOL_BLOCKS = (N_NODES * 32 + TPB - 1) / TPB;

    // ---- CSR build (once; reused by all 3 layers) ----
    cudaMemsetAsync(curd, 0, N_NODES * sizeof(int));
    count_deg_kernel<<<EDGE4_BLOCKS, TPB>>>((const int4*)edge_dst);
    scan_kernel<<<1, 1024>>>();
    scatter_kernel<<<EDGE4_BLOCKS, TPB>>>((const int4*)edge_src, (const int4*)edge_dst);

    // ---- layer 1 (A1 = x, fp32) ----
    gemm_tc_kernel<128, false, false, false, true><<<GEMM_BLOCKS, TPB>>>(
        x, nullptr, Wp[0], nullptr, bp[0], xpd);
    pool_kernel<<<POOL_BLOCKS, TPB>>>();
    gemm_tc_kernel<128, true, true, false, true><<<GEMM_BLOCKS, TPB>>>(
        x, pld, Ws[0], Wn[0], bb[0], h0d);

    // ---- layer 2 (A1 = h0, fp16) ----
    gemm_tc_kernel<128, false, false, true, true><<<GEMM_BLOCKS, TPB>>>(
        h0d, nullptr, Wp[1], nullptr, bp[1], xpd);
    pool_kernel<<<POOL_BLOCKS, TPB>>>();
    gemm_tc_kernel<128, true, true, true, true><<<GEMM_BLOCKS, TPB>>>(
        h0d, pld, Ws[1], Wn[1], bb[1], h1d);

    // ---- layer 3 (A1 = h1, fp16; out = d_out fp32) ----
    gemm_tc_kernel<128, false, false, true, true><<<GEMM_BLOCKS, TPB>>>(
        h1d, nullptr, Wp[2], nullptr, bp[2], xpd);
    pool_kernel<<<POOL_BLOCKS, TPB>>>();
    gemm_tc_kernel<64, true, true, true, false><<<GEMM_BLOCKS, TPB>>>(
        h1d, pld, Ws[2], Wn[2], bb[2], out);
}

// round 6
// speedup vs baseline: 1.3005x; 1.3005x over previous
#include <cuda_runtime.h>
#include <cuda_fp16.h>
#include <math.h>

#define N_NODES 50000
#define N_EDGES 800000
#define DIN 128

// ---------------- scratch (no cudaMalloc allowed) ----------------
__device__ __half g_h0[N_NODES * DIN];
__device__ __half g_h1[N_NODES * DIN];
__device__ __half g_xp[N_NODES * DIN];
__device__ __half g_pooled[N_NODES * DIN];
__device__ float  g_hs[N_NODES * DIN];     // h @ Ws (pre-pool partial)
__device__ int    g_rowptr[N_NODES + 1];
__device__ int    g_cursor[N_NODES];
__device__ int    g_csr[N_EDGES];

struct alignas(8) H4 { __half2 a, b; };

// ---------------- CSR build ----------------
__global__ void count_deg_kernel(const int4* __restrict__ dst4) {
    int i = blockIdx.x * blockDim.x + threadIdx.x;
    if (i < N_EDGES / 4) {
        int4 d = dst4[i];
        atomicAdd(&g_cursor[d.x], 1);
        atomicAdd(&g_cursor[d.y], 1);
        atomicAdd(&g_cursor[d.z], 1);
        atomicAdd(&g_cursor[d.w], 1);
    }
}

// thread-coarsened block scan: 1024 threads x 49 elems, one shuffle scan
__global__ void scan_kernel() {
    const int T = 1024;
    const int CH = (N_NODES + T - 1) / T;  // 49
    int tid = threadIdx.x;
    int start = tid * CH;

    int vals[CH];
    int s = 0;
    #pragma unroll
    for (int j = 0; j < CH; j++) {
        int i = start + j;
        int v = (i < N_NODES) ? g_cursor[i] : 0;
        vals[j] = v; s += v;
    }
    int lane = tid & 31, w = tid >> 5;
    int inc = s;
    #pragma unroll
    for (int off = 1; off < 32; off <<= 1) {
        int t = __shfl_up_sync(0xffffffffu, inc, off);
        if (lane >= off) inc += t;
    }
    __shared__ int wsum[32];
    if (lane == 31) wsum[w] = inc;
    __syncthreads();
    if (w == 0) {
        int x = wsum[lane];
        #pragma unroll
        for (int off = 1; off < 32; off <<= 1) {
            int t = __shfl_up_sync(0xffffffffu, x, off);
            if (lane >= off) x += t;
        }
        wsum[lane] = x;
    }
    __syncthreads();
    int excl = inc - s + (w > 0 ? wsum[w - 1] : 0);
    #pragma unroll
    for (int j = 0; j < CH; j++) {
        int i = start + j;
        if (i < N_NODES) { g_rowptr[i] = excl; g_cursor[i] = excl; excl += vals[j]; }
    }
    if (tid == T - 1) g_rowptr[N_NODES] = excl;
}

__global__ void scatter_kernel(const int4* __restrict__ src4, const int4* __restrict__ dst4) {
    int i = blockIdx.x * blockDim.x + threadIdx.x;
    if (i < N_EDGES / 4) {
        int4 s = src4[i];
        int4 d = dst4[i];
        int p0 = atomicAdd(&g_cursor[d.x], 1);
        int p1 = atomicAdd(&g_cursor[d.y], 1);
        int p2 = atomicAdd(&g_cursor[d.z], 1);
        int p3 = atomicAdd(&g_cursor[d.w], 1);
        g_csr[p0] = s.x; g_csr[p1] = s.y; g_csr[p2] = s.z; g_csr[p3] = s.w;
    }
}

// ---------------- pooling: per-node warp max over CSR neighbors (fp16) --------
// relu output >= 0, so 0-init max == segment_max (and deg==0 -> 0, matching ref)
__global__ void pool_kernel() {
    int node = (blockIdx.x * blockDim.x + threadIdx.x) >> 5;
    int lane = threadIdx.x & 31;
    if (node >= N_NODES) return;
    int s = g_rowptr[node];
    int e = g_rowptr[node + 1];
    __half2 m0 = __float2half2_rn(0.f), m1 = m0;
    int j = s;
    for (; j + 4 <= e; j += 4) {
        int i0 = g_csr[j], i1 = g_csr[j + 1], i2 = g_csr[j + 2], i3 = g_csr[j + 3];
        H4 v0 = *reinterpret_cast<const H4*>(g_xp + (size_t)i0 * DIN + lane * 4);
        H4 v1 = *reinterpret_cast<const H4*>(g_xp + (size_t)i1 * DIN + lane * 4);
        H4 v2 = *reinterpret_cast<const H4*>(g_xp + (size_t)i2 * DIN + lane * 4);
        H4 v3 = *reinterpret_cast<const H4*>(g_xp + (size_t)i3 * DIN + lane * 4);
        m0 = __hmax2(m0, v0.a); m1 = __hmax2(m1, v0.b);
        m0 = __hmax2(m0, v1.a); m1 = __hmax2(m1, v1.b);
        m0 = __hmax2(m0, v2.a); m1 = __hmax2(m1, v2.b);
        m0 = __hmax2(m0, v3.a); m1 = __hmax2(m1, v3.b);
    }
    for (; j < e; j++) {
        int i0 = g_csr[j];
        H4 v = *reinterpret_cast<const H4*>(g_xp + (size_t)i0 * DIN + lane * 4);
        m0 = __hmax2(m0, v.a); m1 = __hmax2(m1, v.b);
    }
    H4 o; o.a = m0; o.b = m1;
    *reinterpret_cast<H4*>(g_pooled + (size_t)node * DIN + lane * 4) = o;
}

// ---------------- fp16 tensor-core primitives ----------------
__device__ __forceinline__ void ldsm_x4(unsigned& r0, unsigned& r1, unsigned& r2, unsigned& r3,
                                        unsigned addr) {
    asm volatile("ldmatrix.sync.aligned.m8n8.x4.shared.b16 {%0,%1,%2,%3}, [%4];"
                 : "=r"(r0), "=r"(r1), "=r"(r2), "=r"(r3) : "r"(addr));
}
__device__ __forceinline__ void ldsm_x4_t(unsigned& r0, unsigned& r1, unsigned& r2, unsigned& r3,
                                          unsigned addr) {
    asm volatile("ldmatrix.sync.aligned.m8n8.x4.trans.shared.b16 {%0,%1,%2,%3}, [%4];"
                 : "=r"(r0), "=r"(r1), "=r"(r2), "=r"(r3) : "r"(addr));
}
__device__ __forceinline__ void mma_f16(float& d0, float& d1, float& d2, float& d3,
                                        unsigned a0, unsigned a1, unsigned a2, unsigned a3,
                                        unsigned b0, unsigned b1) {
    asm volatile(
        "mma.sync.aligned.m16n8k16.row.col.f32.f16.f16.f32 "
        "{%0,%1,%2,%3}, {%4,%5,%6,%7}, {%8,%9}, {%0,%1,%2,%3};"
        : "+f"(d0), "+f"(d1), "+f"(d2), "+f"(d3)
        : "r"(a0), "r"(a1), "r"(a2), "r"(a3), "r"(b0), "r"(b1));
}

// ============ kernel1: fused xp/hs GEMM ============
// grid.y chunk: by<2 -> xp[:, by*64:+64] = relu(A@Wp + bp);
//               by>=2 -> hs[:, (by-2)*64:+64] = A@Ws.
// BM=128, BN=64, BK=32, K=128, 256 threads, 8 warps (4x2), warp tile 32x32.
template <bool A1HALF, int DOUTS>
__global__ void __launch_bounds__(256)
fused1_kernel(const void* __restrict__ Av,
              const float* __restrict__ Wp, const float* __restrict__ bp,
              const float* __restrict__ Ws,
              __half* __restrict__ xp, float* __restrict__ hs)
{
    constexpr int BK = 32;
    constexpr int AST = 40;       // half stride, 80B rows -> conflict-free LDSM
    constexpr int BST = 72;       // 144B rows
    constexpr int ASZ = 128 * AST;
    constexpr int BSZ = BK * BST;

    __shared__ __half AsS[2][ASZ];
    __shared__ __half BsS[2][BSZ];

    const float* A1f = (const float*)Av;
    const __half* A1h = (const __half*)Av;

    int tid = threadIdx.x;
    int lane = tid & 31, wid = tid >> 5;
    int lr = lane >> 2, lc = lane & 3;
    int l15 = lane & 15, lhi8 = (lane >> 4) << 3;
    int wr = wid >> 1, wc = wid & 1;
    int mbase = wr * 32;          // 4 warp-rows of 32
    int nbase = wc * 32;          // 2 warp-cols of 32
    int blockRow = blockIdx.x * 128;
    int by = blockIdx.y;
    bool isWp = by < 2;
    int coff = isWp ? by * 64 : (by - 2) * 64;
    const float* B = (isWp ? Wp : Ws) + coff;
    int ldB = isWp ? 128 : DOUTS;

    float acc[2][4][4];
    #pragma unroll
    for (int mt = 0; mt < 2; mt++)
        #pragma unroll
        for (int nt = 0; nt < 4; nt++)
            #pragma unroll
            for (int r = 0; r < 4; r++) acc[mt][nt][r] = 0.f;

    float4 fav[4];
    uint4  hav[2];
    float4 bvr[2];

    auto ldg_tile = [&](int kt) {
        int kb = kt * BK;
        #pragma unroll
        for (int i = 0; i < 2; i++) {
            int f = tid + i * 256;
            int brow = f >> 4, bc4 = f & 15;
            bvr[i] = *reinterpret_cast<const float4*>(B + (size_t)(kb + brow) * ldB + bc4 * 4);
        }
        if (!A1HALF) {
            #pragma unroll
            for (int i = 0; i < 4; i++) {
                int f = tid + i * 256;
                int row = f >> 3, c4 = f & 7;
                int gr = blockRow + row; if (gr >= N_NODES) gr = N_NODES - 1;
                fav[i] = *reinterpret_cast<const float4*>(A1f + (size_t)gr * DIN + kb + c4 * 4);
            }
        } else {
            #pragma unroll
            for (int i = 0; i < 2; i++) {
                int f = tid + i * 256;
                int row = f >> 2, q = f & 3;
                int gr = blockRow + row; if (gr >= N_NODES) gr = N_NODES - 1;
                hav[i] = *reinterpret_cast<const uint4*>(A1h + (size_t)gr * DIN + kb + q * 8);
            }
        }
    };

    auto sts_tile = [&](int kt) {
        __half* As = AsS[kt & 1];
        __half* Bs = BsS[kt & 1];
        #pragma unroll
        for (int i = 0; i < 2; i++) {
            int f = tid + i * 256;
            int brow = f >> 4, bc4 = f & 15;
            __half2 lo = __floats2half2_rn(bvr[i].x, bvr[i].y);
            __half2 hi = __floats2half2_rn(bvr[i].z, bvr[i].w);
            *reinterpret_cast<__half2*>(Bs + brow * BST + bc4 * 4)     = lo;
            *reinterpret_cast<__half2*>(Bs + brow * BST + bc4 * 4 + 2) = hi;
        }
        if (!A1HALF) {
            #pragma unroll
            for (int i = 0; i < 4; i++) {
                int f = tid + i * 256;
                int row = f >> 3, c4 = f & 7;
                __half2 lo = __floats2half2_rn(fav[i].x, fav[i].y);
                __half2 hi = __floats2half2_rn(fav[i].z, fav[i].w);
                *reinterpret_cast<__half2*>(As + row * AST + c4 * 4)     = lo;
                *reinterpret_cast<__half2*>(As + row * AST + c4 * 4 + 2) = hi;
            }
        } else {
            #pragma unroll
            for (int i = 0; i < 2; i++) {
                int f = tid + i * 256;
                int row = f >> 2, q = f & 3;
                *reinterpret_cast<uint4*>(As + row * AST + q * 8) = hav[i];
            }
        }
    };

    ldg_tile(0);
    sts_tile(0);
    __syncthreads();

    for (int kt = 0; kt < 4; kt++) {
        if (kt + 1 < 4) ldg_tile(kt + 1);

        const __half* As = AsS[kt & 1];
        const __half* Bs = BsS[kt & 1];
        unsigned abase = (unsigned)__cvta_generic_to_shared(As);
        unsigned bbase = (unsigned)__cvta_generic_to_shared(Bs);

        #pragma unroll
        for (int ks = 0; ks < 2; ks++) {
            int kk = ks * 16;
            unsigned af[2][4];
            #pragma unroll
            for (int mt = 0; mt < 2; mt++) {
                unsigned addr = abase + 2 * ((mbase + mt * 16 + l15) * AST + kk + lhi8);
                ldsm_x4(af[mt][0], af[mt][1], af[mt][2], af[mt][3], addr);
            }
            unsigned bf[4][2];
            #pragma unroll
            for (int np = 0; np < 2; np++) {
                unsigned addr = bbase + 2 * ((kk + l15) * BST + nbase + np * 16 + lhi8);
                unsigned r0, r1, r2, r3;
                ldsm_x4_t(r0, r1, r2, r3, addr);
                bf[2 * np][0] = r0; bf[2 * np][1] = r1;
                bf[2 * np + 1][0] = r2; bf[2 * np + 1][1] = r3;
            }
            #pragma unroll
            for (int mt = 0; mt < 2; mt++)
                #pragma unroll
                for (int nt = 0; nt < 4; nt++)
                    mma_f16(acc[mt][nt][0], acc[mt][nt][1], acc[mt][nt][2], acc[mt][nt][3],
                            af[mt][0], af[mt][1], af[mt][2], af[mt][3],
                            bf[nt][0], bf[nt][1]);
        }

        if (kt + 1 < 4) sts_tile(kt + 1);
        __syncthreads();
    }

    // ---- epilogue ----
    #pragma unroll
    for (int mt = 0; mt < 2; mt++) {
        int ra = blockRow + mbase + mt * 16 + lr;
        int rb = ra + 8;
        #pragma unroll
        for (int nt = 0; nt < 4; nt++) {
            int cl = nbase + nt * 8 + 2 * lc;   // 0..63 within chunk
            int gc = coff + cl;                 // global column (chunk offset applied)
            float v0 = acc[mt][nt][0], v1 = acc[mt][nt][1];
            float v2 = acc[mt][nt][2], v3 = acc[mt][nt][3];
            if (isWp) {
                float2 bv = *reinterpret_cast<const float2*>(bp + gc);
                v0 = fmaxf(v0 + bv.x, 0.f); v1 = fmaxf(v1 + bv.y, 0.f);
                v2 = fmaxf(v2 + bv.x, 0.f); v3 = fmaxf(v3 + bv.y, 0.f);
                if (ra < N_NODES)
                    *reinterpret_cast<__half2*>(xp + (size_t)ra * DIN + gc) = __floats2half2_rn(v0, v1);
                if (rb < N_NODES)
                    *reinterpret_cast<__half2*>(xp + (size_t)rb * DIN + gc) = __floats2half2_rn(v2, v3);
            } else {
                // FIX (R5 bug): write to global column gc, not chunk-local cl
                if (ra < N_NODES)
                    *reinterpret_cast<float2*>(hs + (size_t)ra * DOUTS + gc) = make_float2(v0, v1);
                if (rb < N_NODES)
                    *reinterpret_cast<float2*>(hs + (size_t)rb * DOUTS + gc) = make_float2(v2, v3);
            }
        }
    }
}

// ============ kernel2: out = l2norm_relu(hs + pooled@Wn + b) ============
// BM=64, BN=DOUT, BK=32, K=128, 256 threads, 8 warps (4x2), warp tile 16x(BN/2).
template <int DOUT, bool OUTHALF>
__global__ void __launch_bounds__(256)
fused2_kernel(const __half* __restrict__ pooled, const float* __restrict__ Wn,
              const float* __restrict__ bias, const float* __restrict__ hs,
              void* __restrict__ outv)
{
    constexpr int BM = 64, BK = 32, BN = DOUT;
    constexpr int NT = BN / 16;          // 8 (BN=128) or 4 (BN=64)
    constexpr int AST = 40;
    constexpr int BST = BN + 8;          // 136 / 72
    constexpr int ASZ = BM * AST;
    constexpr int BSZ = BK * BST;
    constexpr int BF4 = (BK * BN) / (4 * 256);   // 4 / 2

    __shared__ __half AsS[2][ASZ];
    __shared__ __half BsS[2][BSZ];
    __shared__ float ssbuf[2][BM];

    int tid = threadIdx.x;
    int lane = tid & 31, wid = tid >> 5;
    int lr = lane >> 2, lc = lane & 3;
    int l15 = lane & 15, lhi8 = (lane >> 4) << 3;
    int wr = wid >> 1, wc = wid & 1;
    int mbase = wr * 16;
    int nbase = wc * (BN / 2);
    int blockRow = blockIdx.x * BM;

    float acc[NT][4];
    #pragma unroll
    for (int nt = 0; nt < NT; nt++)
        #pragma unroll
        for (int r = 0; r < 4; r++) acc[nt][r] = 0.f;

    uint4  hav;
    float4 bvr[BF4];

    auto ldg_tile = [&](int kt) {
        int kb = kt * BK;
        #pragma unroll
        for (int i = 0; i < BF4; i++) {
            int f = tid + i * 256;
            int brow = f / (BN / 4), bc4 = f % (BN / 4);
            bvr[i] = *reinterpret_cast<const float4*>(Wn + (size_t)(kb + brow) * BN + bc4 * 4);
        }
        {
            int row = tid >> 2, q = tid & 3;
            int gr = blockRow + row; if (gr >= N_NODES) gr = N_NODES - 1;
            hav = *reinterpret_cast<const uint4*>(pooled + (size_t)gr * DIN + kb + q * 8);
        }
    };

    auto sts_tile = [&](int kt) {
        __half* As = AsS[kt & 1];
        __half* Bs = BsS[kt & 1];
        #pragma unroll
        for (int i = 0; i < BF4; i++) {
            int f = tid + i * 256;
            int brow = f / (BN / 4), bc4 = f % (BN / 4);
            __half2 lo = __floats2half2_rn(bvr[i].x, bvr[i].y);
            __half2 hi = __floats2half2_rn(bvr[i].z, bvr[i].w);
            *reinterpret_cast<__half2*>(Bs + brow * BST + bc4 * 4)     = lo;
            *reinterpret_cast<__half2*>(Bs + brow * BST + bc4 * 4 + 2) = hi;
        }
        {
            int row = tid >> 2, q = tid & 3;
            *reinterpret_cast<uint4*>(As + row * AST + q * 8) = hav;
        }
    };

    ldg_tile(0);
    sts_tile(0);
    __syncthreads();

    for (int kt = 0; kt < 4; kt++) {
        if (kt + 1 < 4) ldg_tile(kt + 1);

        const __half* As = AsS[kt & 1];
        const __half* Bs = BsS[kt & 1];
        unsigned abase = (unsigned)__cvta_generic_to_shared(As);
        unsigned bbase = (unsigned)__cvta_generic_to_shared(Bs);

        #pragma unroll
        for (int ks = 0; ks < 2; ks++) {
            int kk = ks * 16;
            unsigned af[4];
            {
                unsigned addr = abase + 2 * ((mbase + l15) * AST + kk + lhi8);
                ldsm_x4(af[0], af[1], af[2], af[3], addr);
            }
            unsigned bf[NT][2];
            #pragma unroll
            for (int np = 0; np < NT / 2; np++) {
                unsigned addr = bbase + 2 * ((kk + l15) * BST + nbase + np * 16 + lhi8);
                unsigned r0, r1, r2, r3;
                ldsm_x4_t(r0, r1, r2, r3, addr);
                bf[2 * np][0] = r0; bf[2 * np][1] = r1;
                bf[2 * np + 1][0] = r2; bf[2 * np + 1][1] = r3;
            }
            #pragma unroll
            for (int nt = 0; nt < NT; nt++)
                mma_f16(acc[nt][0], acc[nt][1], acc[nt][2], acc[nt][3],
                        af[0], af[1], af[2], af[3], bf[nt][0], bf[nt][1]);
        }

        if (kt + 1 < 4) sts_tile(kt + 1);
        __syncthreads();
    }

    // ---- epilogue: + hs + bias, row L2-norm, relu ----
    int ra = blockRow + mbase + lr;
    int rb = ra + 8;
    #pragma unroll
    for (int nt = 0; nt < NT; nt++) {
        int col = nbase + nt * 8 + 2 * lc;
        float2 bv = *reinterpret_cast<const float2*>(bias + col);
        float2 h0 = (ra < N_NODES) ? *reinterpret_cast<const float2*>(hs + (size_t)ra * DOUT + col)
                                   : make_float2(0.f, 0.f);
        float2 h1 = (rb < N_NODES) ? *reinterpret_cast<const float2*>(hs + (size_t)rb * DOUT + col)
                                   : make_float2(0.f, 0.f);
        acc[nt][0] += bv.x + h0.x; acc[nt][1] += bv.y + h0.y;
        acc[nt][2] += bv.x + h1.x; acc[nt][3] += bv.y + h1.y;
    }

    float ssA = 0.f, ssB = 0.f;
    #pragma unroll
    for (int nt = 0; nt < NT; nt++) {
        ssA += acc[nt][0] * acc[nt][0] + acc[nt][1] * acc[nt][1];
        ssB += acc[nt][2] * acc[nt][2] + acc[nt][3] * acc[nt][3];
    }
    ssA += __shfl_xor_sync(0xffffffffu, ssA, 1);
    ssA += __shfl_xor_sync(0xffffffffu, ssA, 2);
    ssB += __shfl_xor_sync(0xffffffffu, ssB, 1);
    ssB += __shfl_xor_sync(0xffffffffu, ssB, 2);
    int rla = mbase + lr;
    if (lc == 0) { ssbuf[wc][rla] = ssA; ssbuf[wc][rla + 8] = ssB; }
    __syncthreads();
    float inv0 = 1.f / fmaxf(sqrtf(ssbuf[0][rla] + ssbuf[1][rla]), 1e-12f);
    float inv1 = 1.f / fmaxf(sqrtf(ssbuf[0][rla + 8] + ssbuf[1][rla + 8]), 1e-12f);

    #pragma unroll
    for (int nt = 0; nt < NT; nt++) {
        int col = nbase + nt * 8 + 2 * lc;
        float v0 = fmaxf(acc[nt][0] * inv0, 0.f);
        float v1 = fmaxf(acc[nt][1] * inv0, 0.f);
        float v2 = fmaxf(acc[nt][2] * inv1, 0.f);
        float v3 = fmaxf(acc[nt][3] * inv1, 0.f);
        if (OUTHALF) {
            __half* out = (__half*)outv;
            if (ra < N_NODES)
                *reinterpret_cast<__half2*>(out + (size_t)ra * DOUT + col) = __floats2half2_rn(v0, v1);
            if (rb < N_NODES)
                *reinterpret_cast<__half2*>(out + (size_t)rb * DOUT + col) = __floats2half2_rn(v2, v3);
        } else {
            float* out = (float*)outv;
            if (ra < N_NODES)
                *reinterpret_cast<float2*>(out + (size_t)ra * DOUT + col) = make_float2(v0, v1);
            if (rb < N_NODES)
                *reinterpret_cast<float2*>(out + (size_t)rb * DOUT + col) = make_float2(v2, v3);
        }
    }
}

// ---------------- launch ----------------
extern "C" void kernel_launch(void* const* d_in, const int* in_sizes, int n_in,
                              void* d_out, int out_size)
{
    const float* x        = (const float*)d_in[0];
    const int*   edge_src = (const int*)d_in[1];
    const int*   edge_dst = (const int*)d_in[2];

    const float* Wp[3]; const float* bp[3];
    const float* Ws[3]; const float* Wn[3]; const float* bb[3];
    for (int l = 0; l < 3; l++) {
        Wp[l] = (const float*)d_in[3 + 5 * l + 0];
        bp[l] = (const float*)d_in[3 + 5 * l + 1];
        Ws[l] = (const float*)d_in[3 + 5 * l + 2];
        Wn[l] = (const float*)d_in[3 + 5 * l + 3];
        bb[l] = (const float*)d_in[3 + 5 * l + 4];
    }

    float* out = (float*)d_out;

    __half* h0d; cudaGetSymbolAddress((void**)&h0d, g_h0);
    __half* h1d; cudaGetSymbolAddress((void**)&h1d, g_h1);
    __half* xpd; cudaGetSymbolAddress((void**)&xpd, g_xp);
    __half* pld; cudaGetSymbolAddress((void**)&pld, g_pooled);
    float* hsd;  cudaGetSymbolAddress((void**)&hsd, g_hs);
    int* curd;   cudaGetSymbolAddress((void**)&curd, g_cursor);

    const int TPB = 256;
    const int G1_X = (N_NODES + 127) / 128;   // 391
    const int G2_X = (N_NODES + 63) / 64;     // 782
    const int EDGE4_BLOCKS = (N_EDGES / 4 + TPB - 1) / TPB;
    const int POOL_BLOCKS = (N_NODES * 32 + TPB - 1) / TPB;

    // ---- CSR build (once; reused by all 3 layers) ----
    cudaMemsetAsync(curd, 0, N_NODES * sizeof(int));
    count_deg_kernel<<<EDGE4_BLOCKS, TPB>>>((const int4*)edge_dst);
    scan_kernel<<<1, 1024>>>();
    scatter_kernel<<<EDGE4_BLOCKS, TPB>>>((const int4*)edge_src, (const int4*)edge_dst);

    // ---- layer 1 (A = x fp32, dout=128) ----
    fused1_kernel<false, 128><<<dim3(G1_X, 4), TPB>>>(x, Wp[0], bp[0], Ws[0], xpd, hsd);
    pool_kernel<<<POOL_BLOCKS, TPB>>>();
    fused2_kernel<128, true><<<G2_X, TPB>>>(pld, Wn[0], bb[0], hsd, h0d);

    // ---- layer 2 (A = h0 fp16, dout=128) ----
    fused1_kernel<true, 128><<<dim3(G1_X, 4), TPB>>>(h0d, Wp[1], bp[1], Ws[1], xpd, hsd);
    pool_kernel<<<POOL_BLOCKS, TPB>>>();
    fused2_kernel<128, true><<<G2_X, TPB>>>(pld, Wn[1], bb[1], hsd, h1d);

    // ---- layer 3 (A = h1 fp16, dout=64; out fp32) ----
    fused1_kernel<true, 64><<<dim3(G1_X, 3), TPB>>>(h1d, Wp[2], bp[2], Ws[2], xpd, hsd);
    pool_kernel<<<POOL_BLOCKS, TPB>>>();
    fused2_kernel<64, false><<<G2_X, TPB>>>(pld, Wn[2], bb[2], hsd, out);
}